// round 11
// baseline (speedup 1.0000x reference)
#include <cuda_runtime.h>

#define HW   4096     // 64*64
#define HW2  16384    // 128*128

// Scratch (no allocation allowed)
__device__ float g_decp[8*100*HW];    // 8 channel-split partials of conv1x1(de,W_cd)
__device__ float g_gatep[8*4*HW];     // 8 partials of gate pre-activation (lowres)
__device__ float g_encp[4*100*HW2];   // 4 partials of conv1x1(en,W_ce) (+b_ce in s=0)
__device__ float g_dwd[100*HW];       // dw3x3(dec)+b_dw on lowres
__device__ float g_wtT[4*HW2*28];     // normalized weights, pixel-contiguous [b][pix][28]
__device__ float g_det[4*HW*256];     // de transposed: [b][pix][c]

typedef unsigned long long u64;

__device__ __forceinline__ u64 pack2(float x, float y){
    u64 r; asm("mov.b64 %0, {%1, %2};" : "=l"(r) : "f"(x), "f"(y)); return r;
}
__device__ __forceinline__ void unpack2(u64 v, float &x, float &y){
    asm("mov.b64 {%0, %1}, %2;" : "=f"(x), "=f"(y) : "l"(v));
}
__device__ __forceinline__ void ffma2(u64 &d, u64 a, u64 b){
    asm("fma.rn.f32x2 %0, %1, %2, %0;" : "+l"(d) : "l"(a), "l"(b));
}

// ---------------------------------------------------------------------------
// K1: 8-way channel-split conv1x1 of de -> 25 dec partials + gate partial.
// Also emits this split's 32-channel slice of de_t[b][pix][c].
// ---------------------------------------------------------------------------
__global__ __launch_bounds__(256) void k1_dec_gate(
        const float* __restrict__ de, const float* __restrict__ W_cd,
        const float* __restrict__ W_gate)
{
    __shared__ __align__(16) float swf[32*28];
    __shared__ __align__(16) float sT[256*17];

    int tid = threadIdx.x;
    int s = blockIdx.x >> 6;            // split 0..7
    int c0 = s << 5;
    int tbase = (blockIdx.x & 63) << 8;
    int b = tbase >> 12;
    int px0 = tbase & 4095;
    int pix = px0 + tid;

    for (int idx = tid; idx < 32*28; idx += 256){
        int c = idx / 28, r = idx - c*28;
        float w = 0.f;
        if (r < 25)       w = W_cd[r*256 + c0 + c];
        else if (r == 25) w = W_gate[c0 + c];
        swf[idx] = w;
    }
    __syncthreads();

    const float* dp = de + ((b<<8) + c0)*HW + pix;
    const ulonglong2* pw2 = (const ulonglong2*)swf;

    u64 acc[13];
    #pragma unroll
    for (int p=0;p<13;p++) acc[p] = 0ULL;

    int tid17 = tid*17;
    for (int chunk = 0; chunk < 2; chunk++){
        #pragma unroll
        for (int cc = 0; cc < 16; cc++){
            int c = (chunk<<4) + cc;
            float v = dp[c*HW];
            sT[tid17 + cc] = v;
            u64 vd = pack2(v, v);
            const ulonglong2* wc = pw2 + c*7;
            #pragma unroll
            for (int p=0;p<6;p++){
                ulonglong2 w = wc[p];
                ffma2(acc[2*p],   vd, w.x);
                ffma2(acc[2*p+1], vd, w.y);
            }
            ffma2(acc[12], vd, wc[6].x);
        }
        __syncthreads();
        #pragma unroll
        for (int it=0; it<4; it++){
            int v = tid + (it<<8);
            int pxl = v >> 2, q = v & 3;
            int sb = pxl*17 + (q<<2);
            float4 o4 = make_float4(sT[sb], sT[sb+1], sT[sb+2], sT[sb+3]);
            *(float4*)&g_det[(((b<<12) + px0 + pxl)<<8) + c0 + (chunk<<4) + (q<<2)] = o4;
        }
        __syncthreads();
    }

    float o[26];
    #pragma unroll
    for (int p=0;p<13;p++) unpack2(acc[p], o[2*p], o[2*p+1]);
    #pragma unroll
    for (int k=0;k<25;k++) g_decp[((s*100) + b*25 + k)*HW + pix] = o[k];
    g_gatep[((s<<2) + b)*HW + pix] = o[25];
}

// ---------------------------------------------------------------------------
// K2: 4-way channel-split conv1x1 of en -> 25 enc partials (+b_ce in split 0).
// grid 1024 = 4 splits x 256 pixel-blocks, 256 thr.
// ---------------------------------------------------------------------------
__global__ __launch_bounds__(256) void k2_enc(
        const float* __restrict__ en, const float* __restrict__ W_ce,
        const float* __restrict__ b_ce)
{
    __shared__ __align__(16) float swf[64*28];
    int tid = threadIdx.x;
    int s = blockIdx.x >> 8;            // 0..3
    int c0 = s << 6;                    // 64-ch slice
    for (int idx = tid; idx < 64*28; idx += 256){
        int c = idx / 28, r = idx - c*28;
        swf[idx] = (r < 25) ? W_ce[r*256 + c0 + c] : 0.f;
    }
    __syncthreads();

    int t = (blockIdx.x & 255)*256 + tid;   // 65536 pixels
    int b = t >> 14, px = t & 16383;
    const float* ep = en + ((b<<8) + c0)*HW2 + px;
    const ulonglong2* pw2 = (const ulonglong2*)swf;

    u64 acc[13];
    #pragma unroll
    for (int p=0;p<13;p++) acc[p] = 0ULL;

    #pragma unroll 8
    for (int c=0;c<64;c++){
        float v = ep[c*HW2];
        u64 vd = pack2(v, v);
        const ulonglong2* wc = pw2 + c*7;
        #pragma unroll
        for (int p=0;p<6;p++){
            ulonglong2 w = wc[p];
            ffma2(acc[2*p],   vd, w.x);
            ffma2(acc[2*p+1], vd, w.y);
        }
        ffma2(acc[12], vd, wc[6].x);
    }

    float o[26];
    #pragma unroll
    for (int p=0;p<13;p++) unpack2(acc[p], o[2*p], o[2*p+1]);
    #pragma unroll
    for (int k=0;k<25;k++){
        float bias = (s == 0) ? b_ce[k] : 0.f;
        g_encp[(s*100 + b*25 + k)*HW2 + px] = o[k] + bias;
    }
}

// ---------------------------------------------------------------------------
// K3a: dwd[bk] = dw3x3(sum of 8 dec partials) + b_dw[k]  (lowres), tiled.
// ---------------------------------------------------------------------------
__global__ __launch_bounds__(256) void k3a_dwd(
        const float* __restrict__ W_dw, const float* __restrict__ b_dw)
{
    __shared__ float sd[34*34];
    __shared__ float sw[9];
    __shared__ float sbias;

    int tid = threadIdx.x;
    int bk = blockIdx.y;
    int k = bk % 25;
    int tile = blockIdx.x;
    int ty0 = (tile >> 1) << 5, tx0 = (tile & 1) << 5;

    if (tid < 9)  sw[tid] = W_dw[k*9 + tid];
    if (tid == 9) sbias = b_dw[k];

    const float* dpl = g_decp + bk*HW;
    for (int idx = tid; idx < 34*34; idx += 256){
        int r = idx / 34, c = idx - r*34;
        int h = ty0 - 1 + r, w = tx0 - 1 + c;
        float a = 0.f;
        if ((unsigned)h < 64u && (unsigned)w < 64u){
            int o = h*64 + w;
            #pragma unroll
            for (int ss=0;ss<8;ss++) a += dpl[ss*100*HW + o];
        }
        sd[idx] = a;
    }
    __syncthreads();

    #pragma unroll
    for (int it=0; it<4; it++){
        int p = tid + (it<<8);
        int r = p >> 5, c = p & 31;
        const float* sp = sd + r*34 + c;
        float acc = sbias;
        #pragma unroll
        for (int u=0;u<3;u++){
            #pragma unroll
            for (int v=0;v<3;v++) acc = fmaf(sp[u*34+v], sw[u*3+v], acc);
        }
        g_dwd[bk*HW + (ty0+r)*64 + tx0 + c] = acc;
    }
}

// ---------------------------------------------------------------------------
// K3b: fused raw + softmax -> normalized weights. 16x8 hires tile, 512 thr:
// 4 threads/pixel split the 25 kernels 7/6/6/6. Staging sums 4 enc partials.
// Grid (8, 16, 4) = 512 blocks x 16 warps.
// ---------------------------------------------------------------------------
__global__ __launch_bounds__(512) void k3b_softmax(
        const float* __restrict__ W_dw, const float* __restrict__ b_dw)
{
    __shared__ float senc[25*180];   // [k][row 0..9][col 0..17]
    __shared__ float sdwd[25*32];    // [k][lr 0..3][lc 0..7]
    __shared__ float swd[225];
    __shared__ float sbd[25];
    __shared__ float sL[128*27];     // exp(logit) [px][k], pad 27

    int tid = threadIdx.x;
    int b = blockIdx.z;
    int j0 = blockIdx.x << 4;
    int i0 = blockIdx.y << 3;
    const float* e0 = g_encp + (b*25)*HW2;
    const float* e1 = g_encp + (100 + b*25)*HW2;
    const float* e2 = g_encp + (200 + b*25)*HW2;
    const float* e3 = g_encp + (300 + b*25)*HW2;

    for (int idx = tid; idx < 4500; idx += 512){
        int k = idx / 180;
        int rem = idx - k*180;
        int r = rem / 18, c = rem - r*18;
        int gi = i0 - 1 + r, gj = j0 - 1 + c;
        float v = 0.f;
        if ((unsigned)gi < 128u && (unsigned)gj < 128u){
            int o = k*HW2 + (gi<<7) + gj;
            v = (e0[o] + e1[o]) + (e2[o] + e3[o]);
        }
        senc[idx] = v;
    }
    for (int idx = tid; idx < 800; idx += 512){
        int k = idx >> 5, px = idx & 31;
        int lr = px >> 3, lc = px & 7;
        sdwd[idx] = g_dwd[(b*25+k)*HW + ((i0>>1)+lr)*64 + (j0>>1)+lc];
    }
    if (tid < 25) sbd[tid] = b_dw[tid];
    for (int idx = tid; idx < 225; idx += 512) swd[idx] = W_dw[idx];
    __syncthreads();

    int q = tid >> 7, pid = tid & 127;     // q: 0..3 kernel-quarter, pid: pixel
    int tx = pid & 15, ty = pid >> 4;
    int k0 = (q == 0) ? 0 : (7 + 6*(q-1)); // 0,7,13,19
    int kn = (q == 0) ? 7 : 6;
    int dwo = ((ty>>1)<<3) + (tx>>1);

    float r[7];
    for (int kk=0; kk<kn; kk++){
        int k = k0 + kk;
        float acc = sbd[k];
        const float* sp = senc + k*180 + ty*18 + tx;
        const float* wk = swd + k*9;
        #pragma unroll
        for (int u=0;u<3;u++){
            #pragma unroll
            for (int v=0;v<3;v++) acc = fmaf(sp[u*18+v], wk[u*3+v], acc);
        }
        acc += sdwd[(k<<5) + dwo];
        float e = __expf(acc);
        r[kk] = e;
        sL[pid*27 + k] = e;
    }
    __syncthreads();

    const float* lp = sL + pid*27;
    float ssum = 0.f;
    #pragma unroll
    for (int k=0;k<25;k++) ssum += lp[k];
    float inv = 1.f / ssum;
    __syncthreads();   // everyone done reading sL before overwrite

    for (int kk=0; kk<kn; kk++) sL[pid*27 + k0 + kk] = r[kk]*inv;
    __syncthreads();

    // cooperative coalesced store: 128 px x 28 floats each
    float* wTb = g_wtT + b*(HW2*28);
    for (int idx = tid; idx < 3584; idx += 512){
        int px = idx / 28, k = idx - px*28;
        int tty = px >> 4, ttx = px & 15;
        int pix = (i0+tty)*128 + j0 + ttx;
        float v = (k < 25) ? sL[px*27 + k] : 0.f;
        wTb[pix*28 + k] = v;
    }
}

// ---------------------------------------------------------------------------
// K4: carafe + gate blend. 8-way channel split (one 32-ch chunk per block).
// smem 13.8KB -> 16 blocks/SM (100% occ). sde stride 9 float4: 8-px tap reads
// hit all 32 banks. Weights via 7 contiguous LDG.128 from g_wtT.
// Block: 8x4 lowres tile, 128 thr. Grid: (8, 16, 4b*8s) = 4096 blocks.
// ---------------------------------------------------------------------------
__global__ __launch_bounds__(128) void k4_out(
        const float* __restrict__ en, const float* __restrict__ b_gate,
        float* __restrict__ out)
{
    __shared__ __align__(16) float4 sde[96*9];   // [halo px 12x8][8 groups + pad]

    int tid = threadIdx.x;
    int sub = tid & 3, lp = tid >> 2;
    int lw = lp & 7,  lh = lp >> 3;
    int z  = blockIdx.z;
    int b  = z >> 3, s = z & 7;
    int c0 = s << 5;                    // 32-ch slice
    int w0 = blockIdx.x * 8, h0 = blockIdx.y * 4;
    int hcur = h0 + lh, wcur = w0 + lw;
    int i = 2*hcur + (sub >> 1), j = 2*wcur + (sub & 1);

    // stage 96 px x 32 ch from de_t (zero-padded halo): 768 float4
    #pragma unroll
    for (int it = 0; it < 6; it++){
        int idx = tid + (it << 7);       // 0..767
        int px = idx >> 3, g = idx & 7;
        int py = px / 12, pxx = px - py*12;
        int hh = h0 - 2 + py, ww = w0 - 2 + pxx;
        float4 v = make_float4(0.f,0.f,0.f,0.f);
        if ((unsigned)hh < 64u && (unsigned)ww < 64u)
            v = *(const float4*)&g_det[(((b<<12) + (hh<<6) + ww)<<8) + c0 + (g<<2)];
        sde[px*9 + g] = v;
    }

    // normalized weights: 7 contiguous float4 loads
    const float4* wt4 = (const float4*)(g_wtT + (b*HW2 + (i<<7) + j)*28);
    float4 w4[7];
    #pragma unroll
    for (int q=0;q<7;q++) w4[q] = wt4[q];
    u64 wp[25];
    {
        const float* wf = (const float*)w4;
        #pragma unroll
        for (int k=0;k<25;k++) wp[k] = pack2(wf[k], wf[k]);
    }

    // gate (sum of 8 partials + bias)
    int lpix = hcur*64 + wcur;
    float gpre = b_gate[0];
    #pragma unroll
    for (int ss=0;ss<8;ss++) gpre += g_gatep[((ss<<2)+b)*HW + lpix];
    float gt = 1.f / (1.f + __expf(-gpre));
    float ga = 1.f - gt;

    int outbase = (b<<22) + (i<<7) + j;
    int tapbase = (lh*12 + lw)*9;

    __syncthreads();

    const ulonglong2* spb = (const ulonglong2*)sde;
    #pragma unroll
    for (int g = 0; g < 8; g++){
        u64 accA = 0ULL, accB = 0ULL;
        const ulonglong2* sp = spb + tapbase + g;
        #pragma unroll
        for (int dy=0; dy<5; dy++){
            #pragma unroll
            for (int dx=0; dx<5; dx++){
                ulonglong2 tv = sp[(dy*12 + dx)*9];
                ffma2(accA, tv.x, wp[dy*5 + dx]);
                ffma2(accB, tv.y, wp[dy*5 + dx]);
            }
        }
        float a0,a1,a2,a3;
        unpack2(accA, a0, a1); unpack2(accB, a2, a3);
        int ob = outbase + ((c0 + (g<<2)) << 14);
        out[ob]             = fmaf(gt, en[ob],             ga*a0);
        out[ob + (1<<14)]   = fmaf(gt, en[ob + (1<<14)],   ga*a1);
        out[ob + (2<<14)]   = fmaf(gt, en[ob + (2<<14)],   ga*a2);
        out[ob + (3<<14)]   = fmaf(gt, en[ob + (3<<14)],   ga*a3);
    }
}

// ---------------------------------------------------------------------------
extern "C" void kernel_launch(void* const* d_in, const int* in_sizes, int n_in,
                              void* d_out, int out_size)
{
    const float* en     = (const float*)d_in[0];
    const float* de     = (const float*)d_in[1];
    const float* W_gate = (const float*)d_in[2];
    const float* b_gate = (const float*)d_in[3];
    const float* W_ce   = (const float*)d_in[4];
    const float* b_ce   = (const float*)d_in[5];
    const float* W_cd   = (const float*)d_in[6];
    const float* W_dw   = (const float*)d_in[7];
    const float* b_dw   = (const float*)d_in[8];
    float* out = (float*)d_out;

    static cudaStream_t s2 = nullptr;
    static cudaEvent_t  e1 = nullptr, e2 = nullptr;
    if (!s2){
        cudaStreamCreateWithFlags(&s2, cudaStreamNonBlocking);
        cudaEventCreateWithFlags(&e1, cudaEventDisableTiming);
        cudaEventCreateWithFlags(&e2, cudaEventDisableTiming);
    }

    cudaEventRecord(e1, 0);
    cudaStreamWaitEvent(s2, e1, 0);
    k2_enc<<<1024, 256, 0, s2>>>(en, W_ce, b_ce);
    cudaEventRecord(e2, s2);

    k1_dec_gate<<<512, 256>>>(de, W_cd, W_gate);
    k3a_dwd<<<dim3(4, 100), 256>>>(W_dw, b_dw);

    cudaStreamWaitEvent(0, e2, 0);
    k3b_softmax<<<dim3(8, 16, 4), 512>>>(W_dw, b_dw);
    k4_out<<<dim3(8, 16, 32), 128>>>(en, b_gate, out);
}

// round 12
// speedup vs baseline: 1.0896x; 1.0896x over previous
#include <cuda_runtime.h>

#define HW   4096     // 64*64
#define HW2  16384    // 128*128

// Scratch (no allocation allowed)
__device__ float g_decp[8*100*HW];    // 8 channel-split partials of conv1x1(de,W_cd)
__device__ float g_gatep[8*4*HW];     // 8 partials of gate pre-activation (lowres)
__device__ float2 g_gate2[4*HW];      // precomputed (sigmoid, 1-sigmoid) per lowres px
__device__ float g_encp[2*100*HW2];   // 2 partials of conv1x1(en,W_ce) (+b_ce in s=0)
__device__ float g_dwd[100*HW];       // dw3x3(dec)+b_dw on lowres
__device__ float g_wtT[4*HW2*28];     // normalized weights, pixel-contiguous [b][pix][28]
__device__ float g_det[4*HW*256];     // de transposed: [b][pix][c]

typedef unsigned long long u64;

__device__ __forceinline__ u64 pack2(float x, float y){
    u64 r; asm("mov.b64 %0, {%1, %2};" : "=l"(r) : "f"(x), "f"(y)); return r;
}
__device__ __forceinline__ void unpack2(u64 v, float &x, float &y){
    asm("mov.b64 {%0, %1}, %2;" : "=f"(x), "=f"(y) : "l"(v));
}
__device__ __forceinline__ void ffma2(u64 &d, u64 a, u64 b){
    asm("fma.rn.f32x2 %0, %1, %2, %0;" : "+l"(d) : "l"(a), "l"(b));
}

// ---------------------------------------------------------------------------
// K1: 8-way channel-split conv1x1 of de -> 25 dec partials + gate partial.
// Also emits this split's 32-channel slice of de_t[b][pix][c].
// ---------------------------------------------------------------------------
__global__ __launch_bounds__(256) void k1_dec_gate(
        const float* __restrict__ de, const float* __restrict__ W_cd,
        const float* __restrict__ W_gate)
{
    __shared__ __align__(16) float swf[32*28];
    __shared__ __align__(16) float sT[256*17];

    int tid = threadIdx.x;
    int s = blockIdx.x >> 6;            // split 0..7
    int c0 = s << 5;
    int tbase = (blockIdx.x & 63) << 8;
    int b = tbase >> 12;
    int px0 = tbase & 4095;
    int pix = px0 + tid;

    for (int idx = tid; idx < 32*28; idx += 256){
        int c = idx / 28, r = idx - c*28;
        float w = 0.f;
        if (r < 25)       w = W_cd[r*256 + c0 + c];
        else if (r == 25) w = W_gate[c0 + c];
        swf[idx] = w;
    }
    __syncthreads();

    const float* dp = de + ((b<<8) + c0)*HW + pix;
    const ulonglong2* pw2 = (const ulonglong2*)swf;

    u64 acc[13];
    #pragma unroll
    for (int p=0;p<13;p++) acc[p] = 0ULL;

    int tid17 = tid*17;
    for (int chunk = 0; chunk < 2; chunk++){
        #pragma unroll
        for (int cc = 0; cc < 16; cc++){
            int c = (chunk<<4) + cc;
            float v = dp[c*HW];
            sT[tid17 + cc] = v;
            u64 vd = pack2(v, v);
            const ulonglong2* wc = pw2 + c*7;
            #pragma unroll
            for (int p=0;p<6;p++){
                ulonglong2 w = wc[p];
                ffma2(acc[2*p],   vd, w.x);
                ffma2(acc[2*p+1], vd, w.y);
            }
            ffma2(acc[12], vd, wc[6].x);
        }
        __syncthreads();
        #pragma unroll
        for (int it=0; it<4; it++){
            int v = tid + (it<<8);
            int pxl = v >> 2, q = v & 3;
            int sb = pxl*17 + (q<<2);
            float4 o4 = make_float4(sT[sb], sT[sb+1], sT[sb+2], sT[sb+3]);
            *(float4*)&g_det[(((b<<12) + px0 + pxl)<<8) + c0 + (chunk<<4) + (q<<2)] = o4;
        }
        __syncthreads();
    }

    float o[26];
    #pragma unroll
    for (int p=0;p<13;p++) unpack2(acc[p], o[2*p], o[2*p+1]);
    #pragma unroll
    for (int k=0;k<25;k++) g_decp[((s*100) + b*25 + k)*HW + pix] = o[k];
    g_gatep[((s<<2) + b)*HW + pix] = o[25];
}

// ---------------------------------------------------------------------------
// K2: 2-way channel-split conv1x1 of en -> 25 enc partials (+b_ce in split 0).
// ---------------------------------------------------------------------------
__global__ __launch_bounds__(256) void k2_enc(
        const float* __restrict__ en, const float* __restrict__ W_ce,
        const float* __restrict__ b_ce)
{
    __shared__ __align__(16) float swf[128*28];
    int tid = threadIdx.x;
    int s = blockIdx.x >> 8;
    int c0 = s << 7;
    for (int idx = tid; idx < 128*28; idx += 256){
        int c = idx / 28, r = idx - c*28;
        swf[idx] = (r < 25) ? W_ce[r*256 + c0 + c] : 0.f;
    }
    __syncthreads();

    int t = (blockIdx.x & 255)*256 + tid;   // 65536 pixels
    int b = t >> 14, px = t & 16383;
    const float* ep = en + ((b<<8) + c0)*HW2 + px;
    const ulonglong2* pw2 = (const ulonglong2*)swf;

    u64 acc[13];
    #pragma unroll
    for (int p=0;p<13;p++) acc[p] = 0ULL;

    #pragma unroll 8
    for (int c=0;c<128;c++){
        float v = ep[c*HW2];
        u64 vd = pack2(v, v);
        const ulonglong2* wc = pw2 + c*7;
        #pragma unroll
        for (int p=0;p<6;p++){
            ulonglong2 w = wc[p];
            ffma2(acc[2*p],   vd, w.x);
            ffma2(acc[2*p+1], vd, w.y);
        }
        ffma2(acc[12], vd, wc[6].x);
    }

    float o[26];
    #pragma unroll
    for (int p=0;p<13;p++) unpack2(acc[p], o[2*p], o[2*p+1]);
    #pragma unroll
    for (int k=0;k<25;k++){
        float bias = (s == 0) ? b_ce[k] : 0.f;
        g_encp[(s*100 + b*25 + k)*HW2 + px] = o[k] + bias;
    }
}

// ---------------------------------------------------------------------------
// K3a: dwd[bk] = dw3x3(sum of 8 dec partials) + b_dw[k]  (lowres), tiled.
// ---------------------------------------------------------------------------
__global__ __launch_bounds__(256) void k3a_dwd(
        const float* __restrict__ W_dw, const float* __restrict__ b_dw)
{
    __shared__ float sd[34*34];
    __shared__ float sw[9];
    __shared__ float sbias;

    int tid = threadIdx.x;
    int bk = blockIdx.y;
    int k = bk % 25;
    int tile = blockIdx.x;
    int ty0 = (tile >> 1) << 5, tx0 = (tile & 1) << 5;

    if (tid < 9)  sw[tid] = W_dw[k*9 + tid];
    if (tid == 9) sbias = b_dw[k];

    const float* dpl = g_decp + bk*HW;
    for (int idx = tid; idx < 34*34; idx += 256){
        int r = idx / 34, c = idx - r*34;
        int h = ty0 - 1 + r, w = tx0 - 1 + c;
        float a = 0.f;
        if ((unsigned)h < 64u && (unsigned)w < 64u){
            int o = h*64 + w;
            #pragma unroll
            for (int ss=0;ss<8;ss++) a += dpl[ss*100*HW + o];
        }
        sd[idx] = a;
    }
    __syncthreads();

    #pragma unroll
    for (int it=0; it<4; it++){
        int p = tid + (it<<8);
        int r = p >> 5, c = p & 31;
        const float* sp = sd + r*34 + c;
        float acc = sbias;
        #pragma unroll
        for (int u=0;u<3;u++){
            #pragma unroll
            for (int v=0;v<3;v++) acc = fmaf(sp[u*34+v], sw[u*3+v], acc);
        }
        g_dwd[bk*HW + (ty0+r)*64 + tx0 + c] = acc;
    }
}

// ---------------------------------------------------------------------------
// K3g: collapse gate partials -> (sigmoid, 1-sigmoid) float2 per lowres px.
// 16384 threads total.
// ---------------------------------------------------------------------------
__global__ __launch_bounds__(256) void k3g_gate(const float* __restrict__ b_gate)
{
    int t = blockIdx.x*256 + threadIdx.x;    // 0..16383 = b*HW+pix
    float gpre = b_gate[0];
    #pragma unroll
    for (int ss=0;ss<8;ss++) gpre += g_gatep[ss*4*HW + t];
    float gt = 1.f / (1.f + __expf(-gpre));
    g_gate2[t] = make_float2(gt, 1.f - gt);
}

// ---------------------------------------------------------------------------
// K3b: fused raw + softmax -> normalized weights. 16x8 hires tile, 512 thr:
// 4 threads/pixel split the 25 kernels 7/6/6/6. Normalize in smem, then
// cooperative coalesced store to pixel-contiguous g_wtT[b][pix][28].
// Grid (8, 16, 4) = 512 blocks x 16 warps.
// ---------------------------------------------------------------------------
__global__ __launch_bounds__(512) void k3b_softmax(
        const float* __restrict__ W_dw, const float* __restrict__ b_dw)
{
    __shared__ float senc[25*180];   // [k][row 0..9][col 0..17]
    __shared__ float sdwd[25*32];    // [k][lr 0..3][lc 0..7]
    __shared__ float swd[225];
    __shared__ float sbd[25];
    __shared__ float sL[128*27];     // exp(logit) [px][k], pad 27

    int tid = threadIdx.x;
    int b = blockIdx.z;
    int j0 = blockIdx.x << 4;
    int i0 = blockIdx.y << 3;
    const float* e0 = g_encp + (b*25)*HW2;
    const float* e1 = g_encp + (100 + b*25)*HW2;

    for (int idx = tid; idx < 4500; idx += 512){
        int k = idx / 180;
        int rem = idx - k*180;
        int r = rem / 18, c = rem - r*18;
        int gi = i0 - 1 + r, gj = j0 - 1 + c;
        float v = 0.f;
        if ((unsigned)gi < 128u && (unsigned)gj < 128u){
            int o = k*HW2 + (gi<<7) + gj;
            v = e0[o] + e1[o];
        }
        senc[idx] = v;
    }
    for (int idx = tid; idx < 800; idx += 512){
        int k = idx >> 5, px = idx & 31;
        int lr = px >> 3, lc = px & 7;
        sdwd[idx] = g_dwd[(b*25+k)*HW + ((i0>>1)+lr)*64 + (j0>>1)+lc];
    }
    if (tid < 25) sbd[tid] = b_dw[tid];
    for (int idx = tid; idx < 225; idx += 512) swd[idx] = W_dw[idx];
    __syncthreads();

    int q = tid >> 7, pid = tid & 127;     // q: 0..3 kernel-quarter, pid: pixel
    int tx = pid & 15, ty = pid >> 4;
    int k0 = (q == 0) ? 0 : (7 + 6*(q-1)); // 0,7,13,19
    int kn = (q == 0) ? 7 : 6;
    int dwo = ((ty>>1)<<3) + (tx>>1);

    float r[7];
    for (int kk=0; kk<kn; kk++){
        int k = k0 + kk;
        float acc = sbd[k];
        const float* sp = senc + k*180 + ty*18 + tx;
        const float* wk = swd + k*9;
        #pragma unroll
        for (int u=0;u<3;u++){
            #pragma unroll
            for (int v=0;v<3;v++) acc = fmaf(sp[u*18+v], wk[u*3+v], acc);
        }
        acc += sdwd[(k<<5) + dwo];
        float e = __expf(acc);
        r[kk] = e;
        sL[pid*27 + k] = e;
    }
    __syncthreads();

    const float* lp = sL + pid*27;
    float ssum = 0.f;
    #pragma unroll
    for (int k=0;k<25;k++) ssum += lp[k];
    float inv = 1.f / ssum;
    __syncthreads();   // everyone done reading sL before overwrite

    for (int kk=0; kk<kn; kk++) sL[pid*27 + k0 + kk] = r[kk]*inv;
    __syncthreads();

    // cooperative coalesced store: 128 px x 28 floats each
    float* wTb = g_wtT + b*(HW2*28);
    for (int idx = tid; idx < 3584; idx += 512){
        int px = idx / 28, k = idx - px*28;
        int tty = px >> 4, ttx = px & 15;
        int pix = (i0+tty)*128 + j0 + ttx;
        float v = (k < 25) ? sL[px*27 + k] : 0.f;
        wTb[pix*28 + k] = v;
    }
}

// ---------------------------------------------------------------------------
// K4: carafe + gate blend. 4-way channel split (one 64-ch chunk per block).
// Weights via 7 contiguous LDG.128 from g_wtT; gate via one LDG.64 from
// g_gate2. Block: 8x4 lowres tile, 128 thr. Grid: (8, 16, 4b*4s) = 2048.
// ---------------------------------------------------------------------------
__global__ __launch_bounds__(128) void k4_out(
        const float* __restrict__ en, float* __restrict__ out)
{
    __shared__ __align__(16) float4 sde[96*17];

    int tid = threadIdx.x;
    int sub = tid & 3, lp = tid >> 2;
    int lw = lp & 7,  lh = lp >> 3;
    int z  = blockIdx.z;
    int b  = z >> 2, s = z & 3;
    int c0 = s << 6;
    int w0 = blockIdx.x * 8, h0 = blockIdx.y * 4;
    int hcur = h0 + lh, wcur = w0 + lw;
    int i = 2*hcur + (sub >> 1), j = 2*wcur + (sub & 1);

    // stage 96 px x 64 ch from de_t (zero-padded halo)
    #pragma unroll
    for (int it = 0; it < 12; it++){
        int idx = tid + (it << 7);
        int px = idx >> 4, g = idx & 15;
        int py = px / 12, pxx = px - py*12;
        int hh = h0 - 2 + py, ww = w0 - 2 + pxx;
        float4 v = make_float4(0.f,0.f,0.f,0.f);
        if ((unsigned)hh < 64u && (unsigned)ww < 64u)
            v = *(const float4*)&g_det[(((b<<12) + (hh<<6) + ww)<<8) + c0 + (g<<2)];
        sde[px*17 + g] = v;
    }

    // normalized weights: 7 contiguous float4 loads
    const float4* wt4 = (const float4*)(g_wtT + (b*HW2 + (i<<7) + j)*28);
    float4 w4[7];
    #pragma unroll
    for (int q=0;q<7;q++) w4[q] = wt4[q];
    u64 wp[25];
    {
        const float* wf = (const float*)w4;
        #pragma unroll
        for (int k=0;k<25;k++) wp[k] = pack2(wf[k], wf[k]);
    }

    // precomputed gate
    float2 g2 = g_gate2[b*HW + hcur*64 + wcur];
    float gt = g2.x, ga = g2.y;

    int outbase = (b<<22) + (i<<7) + j;
    int tapbase = (lh*12 + lw)*17;

    __syncthreads();

    const ulonglong2* spb = (const ulonglong2*)sde;
    #pragma unroll
    for (int g = 0; g < 16; g++){
        u64 accA = 0ULL, accB = 0ULL;
        const ulonglong2* sp = spb + tapbase + g;
        #pragma unroll
        for (int dy=0; dy<5; dy++){
            #pragma unroll
            for (int dx=0; dx<5; dx++){
                ulonglong2 tv = sp[(dy*12 + dx)*17];
                ffma2(accA, tv.x, wp[dy*5 + dx]);
                ffma2(accB, tv.y, wp[dy*5 + dx]);
            }
        }
        float a0,a1,a2,a3;
        unpack2(accA, a0, a1); unpack2(accB, a2, a3);
        int ob = outbase + ((c0 + (g<<2)) << 14);
        out[ob]             = fmaf(gt, en[ob],             ga*a0);
        out[ob + (1<<14)]   = fmaf(gt, en[ob + (1<<14)],   ga*a1);
        out[ob + (2<<14)]   = fmaf(gt, en[ob + (2<<14)],   ga*a2);
        out[ob + (3<<14)]   = fmaf(gt, en[ob + (3<<14)],   ga*a3);
    }
}

// ---------------------------------------------------------------------------
extern "C" void kernel_launch(void* const* d_in, const int* in_sizes, int n_in,
                              void* d_out, int out_size)
{
    const float* en     = (const float*)d_in[0];
    const float* de     = (const float*)d_in[1];
    const float* W_gate = (const float*)d_in[2];
    const float* b_gate = (const float*)d_in[3];
    const float* W_ce   = (const float*)d_in[4];
    const float* b_ce   = (const float*)d_in[5];
    const float* W_cd   = (const float*)d_in[6];
    const float* W_dw   = (const float*)d_in[7];
    const float* b_dw   = (const float*)d_in[8];
    float* out = (float*)d_out;

    static cudaStream_t s2 = nullptr;
    static cudaEvent_t  e1 = nullptr, e2 = nullptr;
    if (!s2){
        cudaStreamCreateWithFlags(&s2, cudaStreamNonBlocking);
        cudaEventCreateWithFlags(&e1, cudaEventDisableTiming);
        cudaEventCreateWithFlags(&e2, cudaEventDisableTiming);
    }

    cudaEventRecord(e1, 0);
    cudaStreamWaitEvent(s2, e1, 0);
    k2_enc<<<512, 256, 0, s2>>>(en, W_ce, b_ce);
    cudaEventRecord(e2, s2);

    k1_dec_gate<<<512, 256>>>(de, W_cd, W_gate);
    k3a_dwd<<<dim3(4, 100), 256>>>(W_dw, b_dw);
    k3g_gate<<<64, 256>>>(b_gate);

    cudaStreamWaitEvent(0, e2, 0);
    k3b_softmax<<<dim3(8, 16, 4), 512>>>(W_dw, b_dw);
    k4_out<<<dim3(8, 16, 16), 128>>>(en, out);
}

// round 13
// speedup vs baseline: 1.0910x; 1.0013x over previous
#include <cuda_runtime.h>

#define HW   4096     // 64*64
#define HW2  16384    // 128*128

// Scratch (no allocation allowed)
__device__ float g_decp[8*100*HW];    // 8 channel-split partials of conv1x1(de,W_cd)
__device__ float g_gatep[8*4*HW];     // 8 partials of gate pre-activation (lowres)
__device__ float2 g_gate2[4*HW];      // precomputed (sigmoid, 1-sigmoid) per lowres px
__device__ float g_encp[2*100*HW2];   // 2 partials of conv1x1(en,W_ce) (+b_ce in s=0)
__device__ float g_dwd[100*HW];       // dw3x3(dec)+b_dw on lowres
__device__ float g_wtT[4*HW2*28];     // normalized weights, pixel-contiguous [b][pix][28]
__device__ float g_det[4*HW*256];     // de transposed: [b][pix][c]

typedef unsigned long long u64;

__device__ __forceinline__ u64 pack2(float x, float y){
    u64 r; asm("mov.b64 %0, {%1, %2};" : "=l"(r) : "f"(x), "f"(y)); return r;
}
__device__ __forceinline__ void unpack2(u64 v, float &x, float &y){
    asm("mov.b64 {%0, %1}, %2;" : "=f"(x), "=f"(y) : "l"(v));
}
__device__ __forceinline__ void ffma2(u64 &d, u64 a, u64 b){
    asm("fma.rn.f32x2 %0, %1, %2, %0;" : "+l"(d) : "l"(a), "l"(b));
}

// ---------------------------------------------------------------------------
// K1: 8-way channel-split conv1x1 of de -> 25 dec partials + gate partial.
// Also emits this split's 32-channel slice of de_t[b][pix][c].
// ---------------------------------------------------------------------------
__global__ __launch_bounds__(256) void k1_dec_gate(
        const float* __restrict__ de, const float* __restrict__ W_cd,
        const float* __restrict__ W_gate)
{
    __shared__ __align__(16) float swf[32*28];
    __shared__ __align__(16) float sT[256*17];

    int tid = threadIdx.x;
    int s = blockIdx.x >> 6;            // split 0..7
    int c0 = s << 5;
    int tbase = (blockIdx.x & 63) << 8;
    int b = tbase >> 12;
    int px0 = tbase & 4095;
    int pix = px0 + tid;

    for (int idx = tid; idx < 32*28; idx += 256){
        int c = idx / 28, r = idx - c*28;
        float w = 0.f;
        if (r < 25)       w = W_cd[r*256 + c0 + c];
        else if (r == 25) w = W_gate[c0 + c];
        swf[idx] = w;
    }
    __syncthreads();

    const float* dp = de + ((b<<8) + c0)*HW + pix;
    const ulonglong2* pw2 = (const ulonglong2*)swf;

    u64 acc[13];
    #pragma unroll
    for (int p=0;p<13;p++) acc[p] = 0ULL;

    int tid17 = tid*17;
    for (int chunk = 0; chunk < 2; chunk++){
        #pragma unroll
        for (int cc = 0; cc < 16; cc++){
            int c = (chunk<<4) + cc;
            float v = dp[c*HW];
            sT[tid17 + cc] = v;
            u64 vd = pack2(v, v);
            const ulonglong2* wc = pw2 + c*7;
            #pragma unroll
            for (int p=0;p<6;p++){
                ulonglong2 w = wc[p];
                ffma2(acc[2*p],   vd, w.x);
                ffma2(acc[2*p+1], vd, w.y);
            }
            ffma2(acc[12], vd, wc[6].x);
        }
        __syncthreads();
        #pragma unroll
        for (int it=0; it<4; it++){
            int v = tid + (it<<8);
            int pxl = v >> 2, q = v & 3;
            int sb = pxl*17 + (q<<2);
            float4 o4 = make_float4(sT[sb], sT[sb+1], sT[sb+2], sT[sb+3]);
            *(float4*)&g_det[(((b<<12) + px0 + pxl)<<8) + c0 + (chunk<<4) + (q<<2)] = o4;
        }
        __syncthreads();
    }

    float o[26];
    #pragma unroll
    for (int p=0;p<13;p++) unpack2(acc[p], o[2*p], o[2*p+1]);
    #pragma unroll
    for (int k=0;k<25;k++) g_decp[((s*100) + b*25 + k)*HW + pix] = o[k];
    g_gatep[((s<<2) + b)*HW + pix] = o[25];
}

// ---------------------------------------------------------------------------
// K2: 2-way channel-split conv1x1 of en -> 25 enc partials (+b_ce in split 0).
// ---------------------------------------------------------------------------
__global__ __launch_bounds__(256) void k2_enc(
        const float* __restrict__ en, const float* __restrict__ W_ce,
        const float* __restrict__ b_ce)
{
    __shared__ __align__(16) float swf[128*28];
    int tid = threadIdx.x;
    int s = blockIdx.x >> 8;
    int c0 = s << 7;
    for (int idx = tid; idx < 128*28; idx += 256){
        int c = idx / 28, r = idx - c*28;
        swf[idx] = (r < 25) ? W_ce[r*256 + c0 + c] : 0.f;
    }
    __syncthreads();

    int t = (blockIdx.x & 255)*256 + tid;   // 65536 pixels
    int b = t >> 14, px = t & 16383;
    const float* ep = en + ((b<<8) + c0)*HW2 + px;
    const ulonglong2* pw2 = (const ulonglong2*)swf;

    u64 acc[13];
    #pragma unroll
    for (int p=0;p<13;p++) acc[p] = 0ULL;

    #pragma unroll 8
    for (int c=0;c<128;c++){
        float v = ep[c*HW2];
        u64 vd = pack2(v, v);
        const ulonglong2* wc = pw2 + c*7;
        #pragma unroll
        for (int p=0;p<6;p++){
            ulonglong2 w = wc[p];
            ffma2(acc[2*p],   vd, w.x);
            ffma2(acc[2*p+1], vd, w.y);
        }
        ffma2(acc[12], vd, wc[6].x);
    }

    float o[26];
    #pragma unroll
    for (int p=0;p<13;p++) unpack2(acc[p], o[2*p], o[2*p+1]);
    #pragma unroll
    for (int k=0;k<25;k++){
        float bias = (s == 0) ? b_ce[k] : 0.f;
        g_encp[(s*100 + b*25 + k)*HW2 + px] = o[k] + bias;
    }
}

// ---------------------------------------------------------------------------
// K3a: dwd[bk] = dw3x3(sum of 8 dec partials) + b_dw[k]  (lowres), tiled.
// ---------------------------------------------------------------------------
__global__ __launch_bounds__(256) void k3a_dwd(
        const float* __restrict__ W_dw, const float* __restrict__ b_dw)
{
    __shared__ float sd[34*34];
    __shared__ float sw[9];
    __shared__ float sbias;

    int tid = threadIdx.x;
    int bk = blockIdx.y;
    int k = bk % 25;
    int tile = blockIdx.x;
    int ty0 = (tile >> 1) << 5, tx0 = (tile & 1) << 5;

    if (tid < 9)  sw[tid] = W_dw[k*9 + tid];
    if (tid == 9) sbias = b_dw[k];

    const float* dpl = g_decp + bk*HW;
    for (int idx = tid; idx < 34*34; idx += 256){
        int r = idx / 34, c = idx - r*34;
        int h = ty0 - 1 + r, w = tx0 - 1 + c;
        float a = 0.f;
        if ((unsigned)h < 64u && (unsigned)w < 64u){
            int o = h*64 + w;
            #pragma unroll
            for (int ss=0;ss<8;ss++) a += dpl[ss*100*HW + o];
        }
        sd[idx] = a;
    }
    __syncthreads();

    #pragma unroll
    for (int it=0; it<4; it++){
        int p = tid + (it<<8);
        int r = p >> 5, c = p & 31;
        const float* sp = sd + r*34 + c;
        float acc = sbias;
        #pragma unroll
        for (int u=0;u<3;u++){
            #pragma unroll
            for (int v=0;v<3;v++) acc = fmaf(sp[u*34+v], sw[u*3+v], acc);
        }
        g_dwd[bk*HW + (ty0+r)*64 + tx0 + c] = acc;
    }
}

// ---------------------------------------------------------------------------
// K3b: fused raw + softmax -> normalized weights, PLUS gate collapse for this
// tile (threads 0-31 sum the 8 gate partials, sigmoid, store g_gate2 — the
// former k3g kernel folded in). 16x8 hires tile, 512 thr: 4 threads/pixel
// split the 25 kernels 7/6/6/6. Grid (8, 16, 4) = 512 blocks.
// ---------------------------------------------------------------------------
__global__ __launch_bounds__(512) void k3b_softmax(
        const float* __restrict__ W_dw, const float* __restrict__ b_dw,
        const float* __restrict__ b_gate)
{
    __shared__ float senc[25*180];   // [k][row 0..9][col 0..17]
    __shared__ float sdwd[25*32];    // [k][lr 0..3][lc 0..7]
    __shared__ float swd[225];
    __shared__ float sbd[25];
    __shared__ float sL[128*27];     // exp(logit) [px][k], pad 27

    int tid = threadIdx.x;
    int b = blockIdx.z;
    int j0 = blockIdx.x << 4;
    int i0 = blockIdx.y << 3;
    int w0 = j0 >> 1, h0 = i0 >> 1;   // lowres tile origin (8 wide x 4 high)
    const float* e0 = g_encp + (b*25)*HW2;
    const float* e1 = g_encp + (100 + b*25)*HW2;

    // folded k3g: gate collapse for this tile's 32 lowres pixels
    if (tid < 32){
        int lh_ = tid >> 3, lw_ = tid & 7;
        int lpix = (h0 + lh_)*64 + w0 + lw_;
        float gpre = b_gate[0];
        #pragma unroll
        for (int ss=0;ss<8;ss++) gpre += g_gatep[((ss<<2)+b)*HW + lpix];
        float gt = 1.f / (1.f + __expf(-gpre));
        g_gate2[b*HW + lpix] = make_float2(gt, 1.f - gt);
    }

    for (int idx = tid; idx < 4500; idx += 512){
        int k = idx / 180;
        int rem = idx - k*180;
        int r = rem / 18, c = rem - r*18;
        int gi = i0 - 1 + r, gj = j0 - 1 + c;
        float v = 0.f;
        if ((unsigned)gi < 128u && (unsigned)gj < 128u){
            int o = k*HW2 + (gi<<7) + gj;
            v = e0[o] + e1[o];
        }
        senc[idx] = v;
    }
    for (int idx = tid; idx < 800; idx += 512){
        int k = idx >> 5, px = idx & 31;
        int lr = px >> 3, lc = px & 7;
        sdwd[idx] = g_dwd[(b*25+k)*HW + (h0+lr)*64 + w0+lc];
    }
    if (tid < 25) sbd[tid] = b_dw[tid];
    for (int idx = tid; idx < 225; idx += 512) swd[idx] = W_dw[idx];
    __syncthreads();

    int q = tid >> 7, pid = tid & 127;     // q: 0..3 kernel-quarter, pid: pixel
    int tx = pid & 15, ty = pid >> 4;
    int k0 = (q == 0) ? 0 : (7 + 6*(q-1)); // 0,7,13,19
    int kn = (q == 0) ? 7 : 6;
    int dwo = ((ty>>1)<<3) + (tx>>1);

    float r[7];
    for (int kk=0; kk<kn; kk++){
        int k = k0 + kk;
        float acc = sbd[k];
        const float* sp = senc + k*180 + ty*18 + tx;
        const float* wk = swd + k*9;
        #pragma unroll
        for (int u=0;u<3;u++){
            #pragma unroll
            for (int v=0;v<3;v++) acc = fmaf(sp[u*18+v], wk[u*3+v], acc);
        }
        acc += sdwd[(k<<5) + dwo];
        float e = __expf(acc);
        r[kk] = e;
        sL[pid*27 + k] = e;
    }
    __syncthreads();

    const float* lp = sL + pid*27;
    float ssum = 0.f;
    #pragma unroll
    for (int k=0;k<25;k++) ssum += lp[k];
    float inv = 1.f / ssum;
    __syncthreads();   // everyone done reading sL before overwrite

    for (int kk=0; kk<kn; kk++) sL[pid*27 + k0 + kk] = r[kk]*inv;
    __syncthreads();

    // cooperative coalesced store: 128 px x 28 floats each
    float* wTb = g_wtT + b*(HW2*28);
    for (int idx = tid; idx < 3584; idx += 512){
        int px = idx / 28, k = idx - px*28;
        int tty = px >> 4, ttx = px & 15;
        int pix = (i0+tty)*128 + j0 + ttx;
        float v = (k < 25) ? sL[px*27 + k] : 0.f;
        wTb[pix*28 + k] = v;
    }
}

// ---------------------------------------------------------------------------
// K4: carafe + gate blend. 4-way channel split (one 64-ch chunk per block).
// Weights via 7 contiguous LDG.128 from g_wtT; gate via one LDG.64 from
// g_gate2. Block: 8x4 lowres tile, 128 thr. Grid: (8, 16, 4b*4s) = 2048.
// ---------------------------------------------------------------------------
__global__ __launch_bounds__(128) void k4_out(
        const float* __restrict__ en, float* __restrict__ out)
{
    __shared__ __align__(16) float4 sde[96*17];

    int tid = threadIdx.x;
    int sub = tid & 3, lp = tid >> 2;
    int lw = lp & 7,  lh = lp >> 3;
    int z  = blockIdx.z;
    int b  = z >> 2, s = z & 3;
    int c0 = s << 6;
    int w0 = blockIdx.x * 8, h0 = blockIdx.y * 4;
    int hcur = h0 + lh, wcur = w0 + lw;
    int i = 2*hcur + (sub >> 1), j = 2*wcur + (sub & 1);

    // stage 96 px x 64 ch from de_t (zero-padded halo)
    #pragma unroll
    for (int it = 0; it < 12; it++){
        int idx = tid + (it << 7);
        int px = idx >> 4, g = idx & 15;
        int py = px / 12, pxx = px - py*12;
        int hh = h0 - 2 + py, ww = w0 - 2 + pxx;
        float4 v = make_float4(0.f,0.f,0.f,0.f);
        if ((unsigned)hh < 64u && (unsigned)ww < 64u)
            v = *(const float4*)&g_det[(((b<<12) + (hh<<6) + ww)<<8) + c0 + (g<<2)];
        sde[px*17 + g] = v;
    }

    // normalized weights: 7 contiguous float4 loads
    const float4* wt4 = (const float4*)(g_wtT + (b*HW2 + (i<<7) + j)*28);
    float4 w4[7];
    #pragma unroll
    for (int q=0;q<7;q++) w4[q] = wt4[q];
    u64 wp[25];
    {
        const float* wf = (const float*)w4;
        #pragma unroll
        for (int k=0;k<25;k++) wp[k] = pack2(wf[k], wf[k]);
    }

    // precomputed gate
    float2 g2 = g_gate2[b*HW + hcur*64 + wcur];
    float gt = g2.x, ga = g2.y;

    int outbase = (b<<22) + (i<<7) + j;
    int tapbase = (lh*12 + lw)*17;

    __syncthreads();

    const ulonglong2* spb = (const ulonglong2*)sde;
    #pragma unroll
    for (int g = 0; g < 16; g++){
        u64 accA = 0ULL, accB = 0ULL;
        const ulonglong2* sp = spb + tapbase + g;
        #pragma unroll
        for (int dy=0; dy<5; dy++){
            #pragma unroll
            for (int dx=0; dx<5; dx++){
                ulonglong2 tv = sp[(dy*12 + dx)*17];
                ffma2(accA, tv.x, wp[dy*5 + dx]);
                ffma2(accB, tv.y, wp[dy*5 + dx]);
            }
        }
        float a0,a1,a2,a3;
        unpack2(accA, a0, a1); unpack2(accB, a2, a3);
        int ob = outbase + ((c0 + (g<<2)) << 14);
        out[ob]             = fmaf(gt, en[ob],             ga*a0);
        out[ob + (1<<14)]   = fmaf(gt, en[ob + (1<<14)],   ga*a1);
        out[ob + (2<<14)]   = fmaf(gt, en[ob + (2<<14)],   ga*a2);
        out[ob + (3<<14)]   = fmaf(gt, en[ob + (3<<14)],   ga*a3);
    }
}

// ---------------------------------------------------------------------------
extern "C" void kernel_launch(void* const* d_in, const int* in_sizes, int n_in,
                              void* d_out, int out_size)
{
    const float* en     = (const float*)d_in[0];
    const float* de     = (const float*)d_in[1];
    const float* W_gate = (const float*)d_in[2];
    const float* b_gate = (const float*)d_in[3];
    const float* W_ce   = (const float*)d_in[4];
    const float* b_ce   = (const float*)d_in[5];
    const float* W_cd   = (const float*)d_in[6];
    const float* W_dw   = (const float*)d_in[7];
    const float* b_dw   = (const float*)d_in[8];
    float* out = (float*)d_out;

    static cudaStream_t s2 = nullptr;
    static cudaEvent_t  e1 = nullptr, e2 = nullptr;
    if (!s2){
        cudaStreamCreateWithFlags(&s2, cudaStreamNonBlocking);
        cudaEventCreateWithFlags(&e1, cudaEventDisableTiming);
        cudaEventCreateWithFlags(&e2, cudaEventDisableTiming);
    }

    cudaEventRecord(e1, 0);
    cudaStreamWaitEvent(s2, e1, 0);
    k2_enc<<<512, 256, 0, s2>>>(en, W_ce, b_ce);
    cudaEventRecord(e2, s2);

    k1_dec_gate<<<512, 256>>>(de, W_cd, W_gate);
    k3a_dwd<<<dim3(4, 100), 256>>>(W_dw, b_dw);

    cudaStreamWaitEvent(0, e2, 0);
    k3b_softmax<<<dim3(8, 16, 4), 512>>>(W_dw, b_dw, b_gate);
    k4_out<<<dim3(8, 16, 16), 128>>>(en, out);
}

// round 14
// speedup vs baseline: 1.1323x; 1.0379x over previous
#include <cuda_runtime.h>

#define HW   4096     // 64*64
#define HW2  16384    // 128*128

// Scratch (no allocation allowed)
__device__ float g_decp[8*100*HW];    // 8 channel-split partials of conv1x1(de,W_cd)
__device__ float g_gatep[8*4*HW];     // 8 partials of gate pre-activation (lowres)
__device__ float2 g_gate2[4*HW];      // precomputed (sigmoid, 1-sigmoid) per lowres px
__device__ float g_encp[2*100*HW2];   // 2 partials of conv1x1(en,W_ce) (+b_ce in s=0)
__device__ float g_dwd[100*HW];       // dw3x3(dec)+b_dw on lowres
__device__ float g_wtT[4*HW2*28];     // normalized weights, pixel-contiguous [b][pix][28]
__device__ float g_det[4*HW*256];     // de transposed: [b][pix][c]

typedef unsigned long long u64;

__device__ __forceinline__ u64 pack2(float x, float y){
    u64 r; asm("mov.b64 %0, {%1, %2};" : "=l"(r) : "f"(x), "f"(y)); return r;
}
__device__ __forceinline__ void unpack2(u64 v, float &x, float &y){
    asm("mov.b64 {%0, %1}, %2;" : "=f"(x), "=f"(y) : "l"(v));
}
__device__ __forceinline__ void ffma2(u64 &d, u64 a, u64 b){
    asm("fma.rn.f32x2 %0, %1, %2, %0;" : "+l"(d) : "l"(a), "l"(b));
}

// ---------------------------------------------------------------------------
// K1: 8-way channel-split conv1x1 of de -> 25 dec partials + gate partial.
// Also emits this split's 32-channel slice of de_t[b][pix][c].
// ---------------------------------------------------------------------------
__global__ __launch_bounds__(256) void k1_dec_gate(
        const float* __restrict__ de, const float* __restrict__ W_cd,
        const float* __restrict__ W_gate)
{
    __shared__ __align__(16) float swf[32*28];
    __shared__ __align__(16) float sT[256*17];

    int tid = threadIdx.x;
    int s = blockIdx.x >> 6;            // split 0..7
    int c0 = s << 5;
    int tbase = (blockIdx.x & 63) << 8;
    int b = tbase >> 12;
    int px0 = tbase & 4095;
    int pix = px0 + tid;

    for (int idx = tid; idx < 32*28; idx += 256){
        int c = idx / 28, r = idx - c*28;
        float w = 0.f;
        if (r < 25)       w = W_cd[r*256 + c0 + c];
        else if (r == 25) w = W_gate[c0 + c];
        swf[idx] = w;
    }
    __syncthreads();

    const float* dp = de + ((b<<8) + c0)*HW + pix;
    const ulonglong2* pw2 = (const ulonglong2*)swf;

    u64 acc[13];
    #pragma unroll
    for (int p=0;p<13;p++) acc[p] = 0ULL;

    int tid17 = tid*17;
    for (int chunk = 0; chunk < 2; chunk++){
        #pragma unroll
        for (int cc = 0; cc < 16; cc++){
            int c = (chunk<<4) + cc;
            float v = dp[c*HW];
            sT[tid17 + cc] = v;
            u64 vd = pack2(v, v);
            const ulonglong2* wc = pw2 + c*7;
            #pragma unroll
            for (int p=0;p<6;p++){
                ulonglong2 w = wc[p];
                ffma2(acc[2*p],   vd, w.x);
                ffma2(acc[2*p+1], vd, w.y);
            }
            ffma2(acc[12], vd, wc[6].x);
        }
        __syncthreads();
        #pragma unroll
        for (int it=0; it<4; it++){
            int v = tid + (it<<8);
            int pxl = v >> 2, q = v & 3;
            int sb = pxl*17 + (q<<2);
            float4 o4 = make_float4(sT[sb], sT[sb+1], sT[sb+2], sT[sb+3]);
            *(float4*)&g_det[(((b<<12) + px0 + pxl)<<8) + c0 + (chunk<<4) + (q<<2)] = o4;
        }
        __syncthreads();
    }

    float o[26];
    #pragma unroll
    for (int p=0;p<13;p++) unpack2(acc[p], o[2*p], o[2*p+1]);
    #pragma unroll
    for (int k=0;k<25;k++) g_decp[((s*100) + b*25 + k)*HW + pix] = o[k];
    g_gatep[((s<<2) + b)*HW + pix] = o[25];
}

// ---------------------------------------------------------------------------
// K2: 2-way channel-split conv1x1 of en -> 25 enc partials (+b_ce in split 0).
// ---------------------------------------------------------------------------
__global__ __launch_bounds__(256) void k2_enc(
        const float* __restrict__ en, const float* __restrict__ W_ce,
        const float* __restrict__ b_ce)
{
    __shared__ __align__(16) float swf[128*28];
    int tid = threadIdx.x;
    int s = blockIdx.x >> 8;
    int c0 = s << 7;
    for (int idx = tid; idx < 128*28; idx += 256){
        int c = idx / 28, r = idx - c*28;
        swf[idx] = (r < 25) ? W_ce[r*256 + c0 + c] : 0.f;
    }
    __syncthreads();

    int t = (blockIdx.x & 255)*256 + tid;   // 65536 pixels
    int b = t >> 14, px = t & 16383;
    const float* ep = en + ((b<<8) + c0)*HW2 + px;
    const ulonglong2* pw2 = (const ulonglong2*)swf;

    u64 acc[13];
    #pragma unroll
    for (int p=0;p<13;p++) acc[p] = 0ULL;

    #pragma unroll 8
    for (int c=0;c<128;c++){
        float v = ep[c*HW2];
        u64 vd = pack2(v, v);
        const ulonglong2* wc = pw2 + c*7;
        #pragma unroll
        for (int p=0;p<6;p++){
            ulonglong2 w = wc[p];
            ffma2(acc[2*p],   vd, w.x);
            ffma2(acc[2*p+1], vd, w.y);
        }
        ffma2(acc[12], vd, wc[6].x);
    }

    float o[26];
    #pragma unroll
    for (int p=0;p<13;p++) unpack2(acc[p], o[2*p], o[2*p+1]);
    #pragma unroll
    for (int k=0;k<25;k++){
        float bias = (s == 0) ? b_ce[k] : 0.f;
        g_encp[(s*100 + b*25 + k)*HW2 + px] = o[k] + bias;
    }
}

// ---------------------------------------------------------------------------
// K3a: dwd[bk] = dw3x3(sum of 8 dec partials) + b_dw[k]  (lowres), tiled.
// ---------------------------------------------------------------------------
__global__ __launch_bounds__(256) void k3a_dwd(
        const float* __restrict__ W_dw, const float* __restrict__ b_dw)
{
    __shared__ float sd[34*34];
    __shared__ float sw[9];
    __shared__ float sbias;

    int tid = threadIdx.x;
    int bk = blockIdx.y;
    int k = bk % 25;
    int tile = blockIdx.x;
    int ty0 = (tile >> 1) << 5, tx0 = (tile & 1) << 5;

    if (tid < 9)  sw[tid] = W_dw[k*9 + tid];
    if (tid == 9) sbias = b_dw[k];

    const float* dpl = g_decp + bk*HW;
    for (int idx = tid; idx < 34*34; idx += 256){
        int r = idx / 34, c = idx - r*34;
        int h = ty0 - 1 + r, w = tx0 - 1 + c;
        float a = 0.f;
        if ((unsigned)h < 64u && (unsigned)w < 64u){
            int o = h*64 + w;
            #pragma unroll
            for (int ss=0;ss<8;ss++) a += dpl[ss*100*HW + o];
        }
        sd[idx] = a;
    }
    __syncthreads();

    #pragma unroll
    for (int it=0; it<4; it++){
        int p = tid + (it<<8);
        int r = p >> 5, c = p & 31;
        const float* sp = sd + r*34 + c;
        float acc = sbias;
        #pragma unroll
        for (int u=0;u<3;u++){
            #pragma unroll
            for (int v=0;v<3;v++) acc = fmaf(sp[u*34+v], sw[u*3+v], acc);
        }
        g_dwd[bk*HW + (ty0+r)*64 + tx0 + c] = acc;
    }
}

// ---------------------------------------------------------------------------
// K3b: fused raw + softmax -> normalized weights + gate collapse.
// 16x8 hires tile, 512 thr, 4 threads/pixel (25 kernels split 7/6/6/6).
// Staging is DIVISION-FREE: thread -> (k, col) once, walk 10 halo rows with
// constant strides. Grid (8, 16, 4) = 512 blocks.
// ---------------------------------------------------------------------------
__global__ __launch_bounds__(512) void k3b_softmax(
        const float* __restrict__ W_dw, const float* __restrict__ b_dw,
        const float* __restrict__ b_gate)
{
    __shared__ float senc[25*180];   // [k][row 0..9][col 0..17]
    __shared__ float sdwd[25*32];    // [k][lr 0..3][lc 0..7]
    __shared__ float swd[225];
    __shared__ float sbd[25];
    __shared__ float sL[128*27];     // exp(logit) [px][k], pad 27

    int tid = threadIdx.x;
    int b = blockIdx.z;
    int j0 = blockIdx.x << 4;
    int i0 = blockIdx.y << 3;
    int w0 = j0 >> 1, h0 = i0 >> 1;   // lowres tile origin (8 wide x 4 high)
    const float* e0 = g_encp + (b*25)*HW2;
    const float* e1 = g_encp + (100 + b*25)*HW2;

    // folded k3g: gate collapse for this tile's 32 lowres pixels
    if (tid < 32){
        int lh_ = tid >> 3, lw_ = tid & 7;
        int lpix = (h0 + lh_)*64 + w0 + lw_;
        float gpre = b_gate[0];
        #pragma unroll
        for (int ss=0;ss<8;ss++) gpre += g_gatep[((ss<<2)+b)*HW + lpix];
        float gt = 1.f / (1.f + __expf(-gpre));
        g_gate2[b*HW + lpix] = make_float2(gt, 1.f - gt);
    }

    // enc halo staging, division-free: thread owns (k, col), walks 10 rows.
    if (tid < 450){
        int k = tid / 18;               // one division at entry
        int col = tid - k*18;
        int gj = j0 - 1 + col;
        bool jok = (unsigned)gj < 128u;
        const float* e0k = e0 + k*HW2 + gj;
        const float* e1k = e1 + k*HW2 + gj;
        float* d = senc + k*180 + col;
        #pragma unroll
        for (int r = 0; r < 10; r++){
            int gi = i0 - 1 + r;
            float v = 0.f;
            if (jok && (unsigned)gi < 128u){
                int o = gi << 7;
                v = e0k[o] + e1k[o];
            }
            d[r*18] = v;
        }
    }
    // dwd staging (shift-indexed)
    {
        int idx = tid;
        if (idx < 800){
            int k = idx >> 5, px = idx & 31;
            int lr = px >> 3, lc = px & 7;
            sdwd[idx] = g_dwd[(b*25+k)*HW + (h0+lr)*64 + w0+lc];
        }
        idx = tid + 512;
        if (idx < 800){
            int k = idx >> 5, px = idx & 31;
            int lr = px >> 3, lc = px & 7;
            sdwd[idx] = g_dwd[(b*25+k)*HW + (h0+lr)*64 + w0+lc];
        }
    }
    if (tid < 25) sbd[tid] = b_dw[tid];
    if (tid < 225) swd[tid] = W_dw[tid];
    __syncthreads();

    int q = tid >> 7, pid = tid & 127;     // q: 0..3 kernel-quarter, pid: pixel
    int tx = pid & 15, ty = pid >> 4;
    int k0 = (q == 0) ? 0 : (7 + 6*(q-1)); // 0,7,13,19
    int kn = (q == 0) ? 7 : 6;
    int dwo = ((ty>>1)<<3) + (tx>>1);

    float r[7];
    for (int kk=0; kk<kn; kk++){
        int k = k0 + kk;
        float acc = sbd[k];
        const float* sp = senc + k*180 + ty*18 + tx;
        const float* wk = swd + k*9;
        #pragma unroll
        for (int u=0;u<3;u++){
            #pragma unroll
            for (int v=0;v<3;v++) acc = fmaf(sp[u*18+v], wk[u*3+v], acc);
        }
        acc += sdwd[(k<<5) + dwo];
        float e = __expf(acc);
        r[kk] = e;
        sL[pid*27 + k] = e;
    }
    __syncthreads();

    const float* lp = sL + pid*27;
    float ssum = 0.f;
    #pragma unroll
    for (int k=0;k<25;k++) ssum += lp[k];
    float inv = 1.f / ssum;
    __syncthreads();   // everyone done reading sL before overwrite

    for (int kk=0; kk<kn; kk++) sL[pid*27 + k0 + kk] = r[kk]*inv;
    __syncthreads();

    // cooperative coalesced store: 128 px x 28 floats each
    float* wTb = g_wtT + b*(HW2*28);
    for (int idx = tid; idx < 3584; idx += 512){
        int px = idx / 28, k = idx - px*28;
        int tty = px >> 4, ttx = px & 15;
        int pix = (i0+tty)*128 + j0 + ttx;
        float v = (k < 25) ? sL[px*27 + k] : 0.f;
        wTb[pix*28 + k] = v;
    }
}

// ---------------------------------------------------------------------------
// K4: carafe + gate blend. 4-way channel split (one 64-ch chunk per block).
// Weights via 7 contiguous LDG.128 from g_wtT; gate via one LDG.64 from
// g_gate2. Block: 8x4 lowres tile, 128 thr. Grid: (8, 16, 4b*4s) = 2048.
// ---------------------------------------------------------------------------
__global__ __launch_bounds__(128) void k4_out(
        const float* __restrict__ en, float* __restrict__ out)
{
    __shared__ __align__(16) float4 sde[96*17];

    int tid = threadIdx.x;
    int sub = tid & 3, lp = tid >> 2;
    int lw = lp & 7,  lh = lp >> 3;
    int z  = blockIdx.z;
    int b  = z >> 2, s = z & 3;
    int c0 = s << 6;
    int w0 = blockIdx.x * 8, h0 = blockIdx.y * 4;
    int hcur = h0 + lh, wcur = w0 + lw;
    int i = 2*hcur + (sub >> 1), j = 2*wcur + (sub & 1);

    // stage 96 px x 64 ch from de_t (zero-padded halo)
    #pragma unroll
    for (int it = 0; it < 12; it++){
        int idx = tid + (it << 7);
        int px = idx >> 4, g = idx & 15;
        int py = px / 12, pxx = px - py*12;
        int hh = h0 - 2 + py, ww = w0 - 2 + pxx;
        float4 v = make_float4(0.f,0.f,0.f,0.f);
        if ((unsigned)hh < 64u && (unsigned)ww < 64u)
            v = *(const float4*)&g_det[(((b<<12) + (hh<<6) + ww)<<8) + c0 + (g<<2)];
        sde[px*17 + g] = v;
    }

    // normalized weights: 7 contiguous float4 loads
    const float4* wt4 = (const float4*)(g_wtT + (b*HW2 + (i<<7) + j)*28);
    float4 w4[7];
    #pragma unroll
    for (int q=0;q<7;q++) w4[q] = wt4[q];
    u64 wp[25];
    {
        const float* wf = (const float*)w4;
        #pragma unroll
        for (int k=0;k<25;k++) wp[k] = pack2(wf[k], wf[k]);
    }

    // precomputed gate
    float2 g2 = g_gate2[b*HW + hcur*64 + wcur];
    float gt = g2.x, ga = g2.y;

    int outbase = (b<<22) + (i<<7) + j;
    int tapbase = (lh*12 + lw)*17;

    __syncthreads();

    const ulonglong2* spb = (const ulonglong2*)sde;
    #pragma unroll
    for (int g = 0; g < 16; g++){
        u64 accA = 0ULL, accB = 0ULL;
        const ulonglong2* sp = spb + tapbase + g;
        #pragma unroll
        for (int dy=0; dy<5; dy++){
            #pragma unroll
            for (int dx=0; dx<5; dx++){
                ulonglong2 tv = sp[(dy*12 + dx)*17];
                ffma2(accA, tv.x, wp[dy*5 + dx]);
                ffma2(accB, tv.y, wp[dy*5 + dx]);
            }
        }
        float a0,a1,a2,a3;
        unpack2(accA, a0, a1); unpack2(accB, a2, a3);
        int ob = outbase + ((c0 + (g<<2)) << 14);
        out[ob]             = fmaf(gt, en[ob],             ga*a0);
        out[ob + (1<<14)]   = fmaf(gt, en[ob + (1<<14)],   ga*a1);
        out[ob + (2<<14)]   = fmaf(gt, en[ob + (2<<14)],   ga*a2);
        out[ob + (3<<14)]   = fmaf(gt, en[ob + (3<<14)],   ga*a3);
    }
}

// ---------------------------------------------------------------------------
extern "C" void kernel_launch(void* const* d_in, const int* in_sizes, int n_in,
                              void* d_out, int out_size)
{
    const float* en     = (const float*)d_in[0];
    const float* de     = (const float*)d_in[1];
    const float* W_gate = (const float*)d_in[2];
    const float* b_gate = (const float*)d_in[3];
    const float* W_ce   = (const float*)d_in[4];
    const float* b_ce   = (const float*)d_in[5];
    const float* W_cd   = (const float*)d_in[6];
    const float* W_dw   = (const float*)d_in[7];
    const float* b_dw   = (const float*)d_in[8];
    float* out = (float*)d_out;

    static cudaStream_t s2 = nullptr;
    static cudaEvent_t  e1 = nullptr, e2 = nullptr;
    if (!s2){
        cudaStreamCreateWithFlags(&s2, cudaStreamNonBlocking);
        cudaEventCreateWithFlags(&e1, cudaEventDisableTiming);
        cudaEventCreateWithFlags(&e2, cudaEventDisableTiming);
    }

    cudaEventRecord(e1, 0);
    cudaStreamWaitEvent(s2, e1, 0);
    k2_enc<<<512, 256, 0, s2>>>(en, W_ce, b_ce);
    cudaEventRecord(e2, s2);

    k1_dec_gate<<<512, 256>>>(de, W_cd, W_gate);
    k3a_dwd<<<dim3(4, 100), 256>>>(W_dw, b_dw);

    cudaStreamWaitEvent(0, e2, 0);
    k3b_softmax<<<dim3(8, 16, 4), 512>>>(W_dw, b_dw, b_gate);
    k4_out<<<dim3(8, 16, 16), 128>>>(en, out);
}